// round 2
// baseline (speedup 1.0000x reference)
#include <cuda_runtime.h>

#define HW    160
#define NIMG  32
#define NBITS 128
#define SW    168            // smem tile row stride (floats)
#define TH    16             // output rows per block
#define TROWS (TH + 6)       // 22 padded rows
#define BITG  16             // bits per block
#define TILEN (TROWS * SW)   // 3696 floats

typedef unsigned long long u64;

struct __align__(16) BitP2 {
    float2 fx1, omfx1, fx2, omfx2;   // horizontal lerp weights (broadcast pairs)
    float2 B1, A1, B2n, A2n;         // 0.25*(1-fy1), 0.25*fy1, -0.25*(1-fy2), -0.25*fy2
    float2 c;                        // 0.125 - 0.25*th (broadcast)
    int    off1, off2;               // y1*SW + x1
};                                    // 80 bytes

__device__ BitP2 g_params[NBITS];

// ---- packed f32x2 helpers -------------------------------------------------
__device__ __forceinline__ u64 mul2(u64 a, u64 b) {
    u64 r; asm("mul.rn.f32x2 %0, %1, %2;" : "=l"(r) : "l"(a), "l"(b)); return r;
}
__device__ __forceinline__ u64 fma2(u64 a, u64 b, u64 c) {
    u64 r; asm("fma.rn.f32x2 %0, %1, %2, %3;" : "=l"(r) : "l"(a), "l"(b), "l"(c)); return r;
}

// ---------------------------------------------------------------------------
// Setup: replicate reference index math exactly; emit packed per-bit params.
// ---------------------------------------------------------------------------
__global__ void setup_kernel(const float* __restrict__ dx1, const float* __restrict__ dx2,
                             const float* __restrict__ dy1, const float* __restrict__ dy2,
                             const float* __restrict__ th) {
    __shared__ float red[128];
    int t = threadIdx.x;  // 128 threads
    float a = fmaxf(fabsf(dx1[t]), fabsf(dx2[t]));
    float b = fmaxf(fabsf(dy1[t]), fabsf(dy2[t]));
    red[t] = fmaxf(a, b);
    __syncthreads();
    for (int s = 64; s > 0; s >>= 1) {
        if (t < s) red[t] = fmaxf(red[t], red[t + s]);
        __syncthreads();
    }
    float L = red[0];
    int shift = 3 - (int)ceilf(L);   // PAD - p

    BitP2 bp;
    {
        float dx = dx1[t], dy = dy1[t];
        float fdx = floorf(dx), fdy = floorf(dy);
        int x1 = (int)(L + fdx) + shift;   // trunc toward zero == jnp astype(int32)
        int y1 = (int)(L + fdy) + shift;
        x1 = min(max(x1, 0), 5);           // dynamic_slice start clamp
        y1 = min(max(y1, 0), 5);
        bp.off1 = y1 * SW + x1;
        float fx = dx - fdx, fy = dy - fdy;
        bp.fx1   = make_float2(fx, fx);
        bp.omfx1 = make_float2(1.0f - fx, 1.0f - fx);
        bp.A1    = make_float2(0.25f * fy, 0.25f * fy);
        bp.B1    = make_float2(0.25f * (1.0f - fy), 0.25f * (1.0f - fy));
    }
    {
        float dx = dx2[t], dy = dy2[t];
        float fdx = floorf(dx), fdy = floorf(dy);
        int x1 = (int)(L + fdx) + shift;
        int y1 = (int)(L + fdy) + shift;
        x1 = min(max(x1, 0), 5);
        y1 = min(max(y1, 0), 5);
        bp.off2 = y1 * SW + x1;
        float fx = dx - fdx, fy = dy - fdy;
        bp.fx2   = make_float2(fx, fx);
        bp.omfx2 = make_float2(1.0f - fx, 1.0f - fx);
        bp.A2n   = make_float2(-0.25f * fy, -0.25f * fy);
        bp.B2n   = make_float2(-0.25f * (1.0f - fy), -0.25f * (1.0f - fy));
    }
    float cc = fmaf(-0.25f, th[t], 0.125f);
    bp.c = make_float2(cc, cc);
    g_params[t] = bp;
}

// ---------------------------------------------------------------------------
// Main: block = (h-tile of 16 rows, group of 16 bits, image n). 160 threads:
// p = tid%80 -> column pair wp=2p; tid/80 -> row half (8 rows each).
// Twin smem tiles (tB shifted by +1 float) make both lo=(p[x],p[x+1]) and
// hi=(p[x+1],p[x+2]) single aligned LDS.64 for any offset parity.
// Packed f32x2 math; vertical lerp carried across rows.
// ---------------------------------------------------------------------------
__global__ __launch_bounds__(160) void fern_main(const float* __restrict__ x,
                                                 float* __restrict__ out) {
    __shared__ __align__(16) float tA[TILEN];
    __shared__ __align__(16) float tB[TILEN];
    __shared__ BitP2 sp[BITG];

    int tid = threadIdx.x;
    int h0  = blockIdx.x * TH;
    int bg  = blockIdx.y;
    int n   = blockIdx.z;

    // Tile fill straight from x (channel 1), zero-padded; tB shadows tA by +1.
    {
        const float* src = x + ((size_t)n * 3 + 1) * (HW * HW);
        for (int idx = tid; idx < TILEN; idx += 160) {
            int r = idx / SW;
            int c = idx - r * SW;
            int h = h0 + r - 3, wc = c - 3;
            float v = 0.0f;
            if ((unsigned)h < HW && (unsigned)wc < HW)
                v = src[h * HW + wc];
            tA[idx] = v;
            if (idx) tB[idx - 1] = v;
        }
    }
    // Params for this bit group -> smem (16 bits * 80B = 80 int4)
    {
        const int4* ps = (const int4*)(g_params + bg * BITG);
        int4* pd = (int4*)sp;
        for (int i = tid; i < BITG * 5; i += 160) pd[i] = ps[i];
    }
    __syncthreads();

    int p     = tid % 80;
    int wp    = 2 * p;
    int rbase = (tid / 80) * 8;     // 0 or 8: this thread's first output row

    float2* outbase = (float2*)(out + (((size_t)n * NBITS + bg * BITG) * HW + h0) * HW);

    for (int b = 0; b < BITG; ++b) {
        const BitP2& P = sp[b];
        u64 fx1   = *(const u64*)&P.fx1,   omfx1 = *(const u64*)&P.omfx1;
        u64 fx2   = *(const u64*)&P.fx2,   omfx2 = *(const u64*)&P.omfx2;
        u64 B1    = *(const u64*)&P.B1,    A1    = *(const u64*)&P.A1;
        u64 B2n   = *(const u64*)&P.B2n,   A2n   = *(const u64*)&P.A2n;
        u64 cpack = *(const u64*)&P.c;
        int off1 = P.off1, off2 = P.off2;

        int base1 = off1 + wp + rbase * SW;
        int base2 = off2 + wp + rbase * SW;
        const float *lo1, *hi1, *lo2, *hi2;
        if (off1 & 1) { lo1 = tB + base1 - 1; hi1 = tA + base1 + 1; }
        else          { lo1 = tA + base1;     hi1 = tB + base1;     }
        if (off2 & 1) { lo2 = tB + base2 - 1; hi2 = tA + base2 + 1; }
        else          { lo2 = tA + base2;     hi2 = tB + base2;     }

        // carry init: horizontal lerp at this thread's first tile row
        u64 t1 = fma2(fx1, *(const u64*)hi1, mul2(omfx1, *(const u64*)lo1));
        u64 t2 = fma2(fx2, *(const u64*)hi2, mul2(omfx2, *(const u64*)lo2));

        float2* op = outbase + (size_t)b * (HW * HW / 2) + rbase * (HW / 2) + p;

#pragma unroll
        for (int hh = 1; hh <= 8; ++hh) {
            u64 u1 = fma2(fx1, *(const u64*)(hi1 + hh * SW), mul2(omfx1, *(const u64*)(lo1 + hh * SW)));
            u64 u2 = fma2(fx2, *(const u64*)(hi2 + hh * SW), mul2(omfx2, *(const u64*)(lo2 + hh * SW)));

            u64 v = fma2(B1, t1, cpack);
            v = fma2(A1, u1, v);
            v = fma2(B2n, t2, v);
            v = fma2(A2n, u2, v);

            float vx = __uint_as_float((unsigned)v);
            float vy = __uint_as_float((unsigned)(v >> 32));
            float2 o;
            o.x = __saturatef(vx);
            o.y = __saturatef(vy);
            op[(size_t)(hh - 1) * (HW / 2)] = o;

            t1 = u1;
            t2 = u2;
        }
    }
}

// ---------------------------------------------------------------------------
extern "C" void kernel_launch(void* const* d_in, const int* in_sizes, int n_in,
                              void* d_out, int out_size) {
    const float* x   = (const float*)d_in[0];
    const float* dx1 = (const float*)d_in[1];
    const float* dx2 = (const float*)d_in[2];
    const float* dy1 = (const float*)d_in[3];
    const float* dy2 = (const float*)d_in[4];
    const float* th  = (const float*)d_in[5];

    setup_kernel<<<1, 128>>>(dx1, dx2, dy1, dy2, th);

    dim3 grid(HW / TH, NBITS / BITG, NIMG);
    fern_main<<<grid, 160>>>(x, (float*)d_out);
}